// round 4
// baseline (speedup 1.0000x reference)
#include <cuda_runtime.h>
#include <cuda_bf16.h>

// LightConv1d: out[b,c,t] = sum_{k=0..6} softmax(w[h])[k] * x[b,c,t-6+k] + bias[h]
// h = c % 16. Shapes: x [8,1024,4096] f32, weight [16,1,7] f32, bias [16] f32.
//
// Persistent-grid streaming version: grid = 148 SMs * 8 CTAs = 1184 resident
// CTAs, each looping rows with stride 1184 (no wave transitions, loads stay
// in flight across iterations). 1184 % 16 == 0 -> head index is constant per
// CTA, so the softmax is computed once per thread outside the row loop.
// Halo comes from overlapping global loads that hit lines neighbor lanes are
// already fetching (L1/L2 merge, no extra DRAM traffic).

#define T_LEN 4096
#define KSZ   7
#define NROWS (8 * 1024)
#define NTHREADS 256
#define NSEG 4                 // 256 threads * 4 segs * 4 floats = 4096 = one row
#define GRID_PERSIST (148 * 8) // 1184 resident CTAs

__global__ __launch_bounds__(NTHREADS, 8)
void lightconv1d_kernel(const float* __restrict__ x,
                        const float* __restrict__ weight,
                        const float* __restrict__ bias,
                        float* __restrict__ out)
{
    const int tid = threadIdx.x;

    // h = row % 16 is invariant across this CTA's rows (stride 1184 % 16 == 0).
    const int h = blockIdx.x & 15;

    // Per-thread softmax of the 7 shared weights for this head (once per CTA).
    float wk[KSZ];
    float m = -1e30f;
    #pragma unroll
    for (int k = 0; k < KSZ; ++k) {
        wk[k] = __ldg(&weight[h * KSZ + k]);
        m = fmaxf(m, wk[k]);
    }
    float sum = 0.0f;
    #pragma unroll
    for (int k = 0; k < KSZ; ++k) {
        wk[k] = expf(wk[k] - m);
        sum += wk[k];
    }
    const float inv = 1.0f / sum;
    #pragma unroll
    for (int k = 0; k < KSZ; ++k) wk[k] *= inv;
    const float bv = __ldg(&bias[h]);

    #pragma unroll 1
    for (int row = blockIdx.x; row < NROWS; row += GRID_PERSIST) {
        const float* __restrict__ xr = x + (size_t)row * T_LEN;
        float* __restrict__ orow     = out + (size_t)row * T_LEN;

        // Front-batch the 4 main loads (MLP_p1 = 4, coalesced 512B/warp-instr).
        float4 v[NSEG];
        #pragma unroll
        for (int seg = 0; seg < NSEG; ++seg)
            v[seg] = reinterpret_cast<const float4*>(xr)[tid + NTHREADS * seg];

        #pragma unroll
        for (int seg = 0; seg < NSEG; ++seg) {
            const int t0 = seg * (NTHREADS * 4) + tid * 4;

            // win[i] = x[t0 - 6 + i], i = 0..9 ; win[6..9] already in v[seg].
            float win[10];
            if (t0 >= 8) {
                // (t0-6)*4 bytes is 8B-aligned, (t0-4)*4 is 16B-aligned.
                const float2 a = *reinterpret_cast<const float2*>(xr + t0 - 6);
                const float4 b = *reinterpret_cast<const float4*>(xr + t0 - 4);
                win[0] = a.x; win[1] = a.y;
                win[2] = b.x; win[3] = b.y; win[4] = b.z; win[5] = b.w;
            } else {
                // Only seg==0, tid<2: causal zero padding at the row start.
                #pragma unroll
                for (int i = 0; i < 6; ++i) {
                    const int idx = t0 - 6 + i;
                    win[i] = (idx >= 0) ? xr[idx] : 0.0f;
                }
            }
            win[6] = v[seg].x; win[7] = v[seg].y; win[8] = v[seg].z; win[9] = v[seg].w;

            float acc0 = bv, acc1 = bv, acc2 = bv, acc3 = bv;
            #pragma unroll
            for (int k = 0; k < KSZ; ++k) {
                acc0 = fmaf(wk[k], win[k + 0], acc0);
                acc1 = fmaf(wk[k], win[k + 1], acc1);
                acc2 = fmaf(wk[k], win[k + 2], acc2);
                acc3 = fmaf(wk[k], win[k + 3], acc3);
            }
            float4 r;
            r.x = acc0; r.y = acc1; r.z = acc2; r.w = acc3;
            reinterpret_cast<float4*>(orow)[tid + NTHREADS * seg] = r;
        }
    }
}

extern "C" void kernel_launch(void* const* d_in, const int* in_sizes, int n_in,
                              void* d_out, int out_size)
{
    const float* x      = (const float*)d_in[0];
    const float* weight = (const float*)d_in[1];
    const float* bias   = (const float*)d_in[2];
    float* out          = (float*)d_out;

    lightconv1d_kernel<<<GRID_PERSIST, NTHREADS>>>(x, weight, bias, out);
}

// round 5
// speedup vs baseline: 1.0211x; 1.0211x over previous
#include <cuda_runtime.h>
#include <cuda_bf16.h>

// LightConv1d: out[b,c,t] = sum_{k=0..6} softmax(w[h])[k] * x[b,c,t-6+k] + bias[h]
// h = c % 16. Shapes: x [8,1024,4096] f32, weight [16,1,7] f32, bias [16] f32.
//
// One CTA per row (8192 CTAs; hardware overlaps CTA waves). Each thread owns
// 16 CONTIGUOUS elements (4 contiguous float4s) -> only one (float2+float4)
// halo load pair per 16 outputs, and 6 front-batched LDGs per thread for MLP.
// Halo lines are the same lines neighbor lanes fetch -> L1/L2 merge, no extra
// DRAM traffic. No SMEM, no barriers.

#define T_LEN 4096
#define KSZ   7
#define NROWS (8 * 1024)
#define NTHREADS 256   // 256 threads * 16 elements = 4096 = one full row

__global__ __launch_bounds__(NTHREADS)
void lightconv1d_kernel(const float* __restrict__ x,
                        const float* __restrict__ weight,
                        const float* __restrict__ bias,
                        float* __restrict__ out)
{
    const int row = blockIdx.x;          // b*1024 + c
    const int tid = threadIdx.x;
    const int t0  = tid * 16;            // first output index for this thread

    const float* __restrict__ xr = x + (size_t)row * T_LEN;
    float* __restrict__ orow     = out + (size_t)row * T_LEN;

    // ---- Front-batch all global loads (6 independent LDGs in flight) ----
    // xv[i] = x[t0 - 6 + i], i = 0..21
    float4 m0 = reinterpret_cast<const float4*>(xr + t0)[0];
    float4 m1 = reinterpret_cast<const float4*>(xr + t0)[1];
    float4 m2 = reinterpret_cast<const float4*>(xr + t0)[2];
    float4 m3 = reinterpret_cast<const float4*>(xr + t0)[3];

    float h0, h1, h2, h3, h4, h5;        // x[t0-6 .. t0-1]
    if (t0 >= 8) {
        const float2 a = *reinterpret_cast<const float2*>(xr + t0 - 6); // 8B aligned
        const float4 b = *reinterpret_cast<const float4*>(xr + t0 - 4); // 16B aligned
        h0 = a.x; h1 = a.y;
        h2 = b.x; h3 = b.y; h4 = b.z; h5 = b.w;
    } else {
        // Only tid == 0: causal zero padding at the row start.
        h0 = h1 = h2 = h3 = h4 = h5 = 0.0f;
    }

    // ---- Softmax of the 7 shared weights for this head (L1-resident) ----
    const int h = row & 15;              // c % 16
    float wk[KSZ];
    float mx = -1e30f;
    #pragma unroll
    for (int k = 0; k < KSZ; ++k) {
        wk[k] = __ldg(&weight[h * KSZ + k]);
        mx = fmaxf(mx, wk[k]);
    }
    float sum = 0.0f;
    #pragma unroll
    for (int k = 0; k < KSZ; ++k) {
        wk[k] = expf(wk[k] - mx);
        sum += wk[k];
    }
    const float inv = 1.0f / sum;
    #pragma unroll
    for (int k = 0; k < KSZ; ++k) wk[k] *= inv;
    const float bv = __ldg(&bias[h]);

    // ---- Assemble the 22-float window and compute 16 outputs ----
    float xv[22];
    xv[0] = h0;  xv[1] = h1;  xv[2] = h2;  xv[3] = h3;  xv[4] = h4;  xv[5] = h5;
    xv[6]  = m0.x; xv[7]  = m0.y; xv[8]  = m0.z; xv[9]  = m0.w;
    xv[10] = m1.x; xv[11] = m1.y; xv[12] = m1.z; xv[13] = m1.w;
    xv[14] = m2.x; xv[15] = m2.y; xv[16] = m2.z; xv[17] = m2.w;
    xv[18] = m3.x; xv[19] = m3.y; xv[20] = m3.z; xv[21] = m3.w;

    #pragma unroll
    for (int g = 0; g < 4; ++g) {        // 4 output float4s
        float a0 = bv, a1 = bv, a2 = bv, a3 = bv;
        #pragma unroll
        for (int k = 0; k < KSZ; ++k) {
            a0 = fmaf(wk[k], xv[g * 4 + 0 + k], a0);
            a1 = fmaf(wk[k], xv[g * 4 + 1 + k], a1);
            a2 = fmaf(wk[k], xv[g * 4 + 2 + k], a2);
            a3 = fmaf(wk[k], xv[g * 4 + 3 + k], a3);
        }
        float4 r; r.x = a0; r.y = a1; r.z = a2; r.w = a3;
        reinterpret_cast<float4*>(orow + t0)[g] = r;
    }
}

extern "C" void kernel_launch(void* const* d_in, const int* in_sizes, int n_in,
                              void* d_out, int out_size)
{
    const float* x      = (const float*)d_in[0];
    const float* weight = (const float*)d_in[1];
    const float* bias   = (const float*)d_in[2];
    float* out          = (float*)d_out;

    lightconv1d_kernel<<<NROWS, NTHREADS>>>(x, weight, bias, out);
}

// round 6
// speedup vs baseline: 1.2125x; 1.1875x over previous
#include <cuda_runtime.h>
#include <cuda_bf16.h>

// LightConv1d: out[b,c,t] = sum_{k=0..6} softmax(w[h])[k] * x[b,c,t-6+k] + bias[h]
// h = c % 16. Shapes: x [8,1024,4096] f32, weight [16,1,7] f32, bias [16] f32.
//
// One CTA per row, block-strided float4 per thread (perfect coalescing:
// 4 lines per LDG.128 warp instruction). The 6-float causal halo comes from
// WARP SHUFFLES of neighbor lanes' registers (lane l-1 holds x[t0-4..t0-1],
// lane l-2 holds x[t0-6..t0-5]) instead of extra global loads -> no L1tex
// wavefronts for the halo. Only lanes 0-1 (cross-warp boundary) do a small
// predicated global halo load. No SMEM, no barriers.

#define T_LEN 4096
#define KSZ   7
#define NROWS (8 * 1024)
#define NTHREADS 256
#define NSEG 4   // 256 threads * 4 segs * 4 floats = 4096 = one full row
#define FULLMASK 0xffffffffu

__global__ __launch_bounds__(NTHREADS)
void lightconv1d_kernel(const float* __restrict__ x,
                        const float* __restrict__ weight,
                        const float* __restrict__ bias,
                        float* __restrict__ out)
{
    const int row  = blockIdx.x;         // b*1024 + c
    const int tid  = threadIdx.x;
    const int lane = tid & 31;

    const float* __restrict__ xr = x + (size_t)row * T_LEN;
    float* __restrict__ orow     = out + (size_t)row * T_LEN;

    // Front-batch the 4 coalesced main loads (MLP_p1 = 4).
    float4 v[NSEG];
    #pragma unroll
    for (int seg = 0; seg < NSEG; ++seg)
        v[seg] = reinterpret_cast<const float4*>(xr)[tid + NTHREADS * seg];

    // Softmax of the 7 shared weights for this head (L1-resident).
    const int h = row & 15;              // c % 16
    float wk[KSZ];
    float mx = -1e30f;
    #pragma unroll
    for (int k = 0; k < KSZ; ++k) {
        wk[k] = __ldg(&weight[h * KSZ + k]);
        mx = fmaxf(mx, wk[k]);
    }
    float sum = 0.0f;
    #pragma unroll
    for (int k = 0; k < KSZ; ++k) {
        wk[k] = expf(wk[k] - mx);
        sum += wk[k];
    }
    const float inv = 1.0f / sum;
    #pragma unroll
    for (int k = 0; k < KSZ; ++k) wk[k] *= inv;
    const float bv = __ldg(&bias[h]);

    #pragma unroll
    for (int seg = 0; seg < NSEG; ++seg) {
        const int t0 = seg * (NTHREADS * 4) + tid * 4;

        // win[i] = x[t0 - 6 + i], i = 0..9.
        float win[10];
        // Halo from neighbor lanes' registers:
        //   lane l-1 holds x[t0-4..t0-1], lane l-2 holds x[t0-8..t0-5].
        win[2] = __shfl_up_sync(FULLMASK, v[seg].x, 1);
        win[3] = __shfl_up_sync(FULLMASK, v[seg].y, 1);
        win[4] = __shfl_up_sync(FULLMASK, v[seg].z, 1);
        win[5] = __shfl_up_sync(FULLMASK, v[seg].w, 1);
        win[0] = __shfl_up_sync(FULLMASK, v[seg].z, 2);
        win[1] = __shfl_up_sync(FULLMASK, v[seg].w, 2);

        // Cross-warp boundary lanes patch their halo from global memory
        // (those lines are L1/L2-resident: the previous warp just loaded them).
        if (lane == 0) {
            if (t0 >= 8) {
                const float2 a = *reinterpret_cast<const float2*>(xr + t0 - 6);
                const float4 b = *reinterpret_cast<const float4*>(xr + t0 - 4);
                win[0] = a.x; win[1] = a.y;
                win[2] = b.x; win[3] = b.y; win[4] = b.z; win[5] = b.w;
            } else {
                // tid==0, seg==0: causal zero padding.
                win[0] = win[1] = win[2] = win[3] = win[4] = win[5] = 0.0f;
            }
        } else if (lane == 1) {
            // delta-2 shuffle invalid for lane 1 only; win[2..5] are fine.
            if (t0 >= 8) {
                const float2 a = *reinterpret_cast<const float2*>(xr + t0 - 6);
                win[0] = a.x; win[1] = a.y;
            } else {
                // tid==1, seg==0: x[-2], x[-1] -> zeros.
                win[0] = win[1] = 0.0f;
            }
        }

        win[6] = v[seg].x; win[7] = v[seg].y; win[8] = v[seg].z; win[9] = v[seg].w;

        float a0 = bv, a1 = bv, a2 = bv, a3 = bv;
        #pragma unroll
        for (int k = 0; k < KSZ; ++k) {
            a0 = fmaf(wk[k], win[k + 0], a0);
            a1 = fmaf(wk[k], win[k + 1], a1);
            a2 = fmaf(wk[k], win[k + 2], a2);
            a3 = fmaf(wk[k], win[k + 3], a3);
        }
        float4 r; r.x = a0; r.y = a1; r.z = a2; r.w = a3;
        reinterpret_cast<float4*>(orow)[tid + NTHREADS * seg] = r;
    }
}

extern "C" void kernel_launch(void* const* d_in, const int* in_sizes, int n_in,
                              void* d_out, int out_size)
{
    const float* x      = (const float*)d_in[0];
    const float* weight = (const float*)d_in[1];
    const float* bias   = (const float*)d_in[2];
    float* out          = (float*)d_out;

    lightconv1d_kernel<<<NROWS, NTHREADS>>>(x, weight, bias, out);
}